// round 2
// baseline (speedup 1.0000x reference)
#include <cuda_runtime.h>
#include <math.h>

#define EDGES 320000
#define NODES 10000

// ---------------- scratch (feature-major: [feature][edge]) ----------------
static __device__ float g_fcut[EDGES];
static __device__ float g_Y[3 * EDGES];          // y1,y2,y3 = sqrt3*unit
static __device__ float g_lat[128 * EDGES];
static __device__ float g_wedge[64 * EDGES];
static __device__ float g_scal0[64 * EDGES];
static __device__ float g_scal1[64 * EDGES];
static __device__ float g_smix[32 * EDGES];
static __device__ float g_vmix[96 * EDGES];      // [(m*3+d)][e]
static __device__ float g_env[NODES * 128];      // [node][m*4+ch]
static __device__ float g_env1[NODES * 128];

// ---------------- constants ----------------
#define INV_RMAX     0.2f
#define SQRT3_C      1.7320508075688772f
#define INV_SQRT3_C  0.5773502691896258f
#define INV_SQRT2_C  0.7071067811865476f
#define ISN          0.17677669529663687f   // 1/sqrt(32)
#define C_OLD        0.8944271909999159f    // 1/sqrt(1.25)
#define C_NEW        0.4472135954999579f
#define INV_S40      0.15811388300841897f
#define INV_S64      0.125f
#define INV_S128     0.08838834764831845f
#define INV_S192     0.07216878364870323f
#define INV_S96      0.10206207261596577f
#define BESSEL_C     0.6324555320336759f    // sqrt(2/5)
#define PI_F         3.14159265358979323846f

__device__ __forceinline__ float silu_f(float x) {
    return __fdividef(x, 1.0f + __expf(-x));
}

// GEMV accumulate: x streamed from a (local) array, acc in registers.
template<int NIN, int NOUT>
__device__ __forceinline__ void gemv_local(const float* x, const float* __restrict__ W, float* acc) {
#pragma unroll 4
    for (int k = 0; k < NIN; k++) {
        float xk = x[k];
        const float4* w = reinterpret_cast<const float4*>(W + k * NOUT);
#pragma unroll
        for (int j = 0; j < NOUT / 4; j++) {
            float4 wv = __ldg(w + j);
            acc[4 * j + 0] += xk * wv.x;
            acc[4 * j + 1] += xk * wv.y;
            acc[4 * j + 2] += xk * wv.z;
            acc[4 * j + 3] += xk * wv.w;
        }
    }
}

// GEMV accumulate: x streamed from feature-major global scratch (coalesced).
template<int NIN, int NOUT>
__device__ __forceinline__ void gemv_global(const float* __restrict__ xg, int e,
                                            const float* __restrict__ W, float* acc) {
#pragma unroll 4
    for (int k = 0; k < NIN; k++) {
        float xk = xg[k * EDGES + e];
        const float4* w = reinterpret_cast<const float4*>(W + k * NOUT);
#pragma unroll
        for (int j = 0; j < NOUT / 4; j++) {
            float4 wv = __ldg(w + j);
            acc[4 * j + 0] += xk * wv.x;
            acc[4 * j + 1] += xk * wv.y;
            acc[4 * j + 2] += xk * wv.z;
            acc[4 * j + 3] += xk * wv.w;
        }
    }
}

// ---------------- zero init ----------------
__global__ void kZero(float* __restrict__ out) {
    int i = blockIdx.x * blockDim.x + threadIdx.x;
    if (i < NODES * 128) {
        g_env[i] = 0.0f;
        g_env1[i] = 0.0f;
        out[i] = 0.0f;
    }
}

// ---------------- pass A: geometry + two-body MLP + Wenv0 + env atomics ----------------
__global__ __launch_bounds__(256) void kA(
    const float* __restrict__ coord, const float* __restrict__ attrs,
    const int* __restrict__ eidx,
    const float* __restrict__ W0, const float* __restrict__ W1,
    const float* __restrict__ W2, const float* __restrict__ Wenv0)
{
    int e = blockIdx.x * blockDim.x + threadIdx.x;
    if (e >= EDGES) return;
    int s = eidx[e];
    int c = eidx[EDGES + e];

    float vx = coord[3 * c + 0] - coord[3 * s + 0];
    float vy = coord[3 * c + 1] - coord[3 * s + 1];
    float vz = coord[3 * c + 2] - coord[3 * s + 2];
    float r2 = vx * vx + vy * vy + vz * vz + 1e-12f;
    float r = sqrtf(r2);
    float u = r * INV_RMAX;
    float u2 = u * u;
    float u6 = u2 * u2 * u2;
    float fcut = 1.0f - 28.0f * u6 + 48.0f * u6 * u - 21.0f * u6 * u2;
    if (u >= 1.0f) fcut = 0.0f;
    float rinv = 1.0f / r;
    float y1 = SQRT3_C * vx * rinv;
    float y2 = SQRT3_C * vy * rinv;
    float y3 = SQRT3_C * vz * rinv;

    g_fcut[e] = fcut;
    g_Y[0 * EDGES + e] = y1;
    g_Y[1 * EDGES + e] = y2;
    g_Y[2 * EDGES + e] = y3;

    float x0[40];
#pragma unroll
    for (int k = 0; k < 16; k++) x0[k] = attrs[16 * c + k];
#pragma unroll
    for (int k = 0; k < 16; k++) x0[16 + k] = attrs[16 * s + k];
    float arg = PI_F * u;
#pragma unroll
    for (int n = 1; n <= 8; n++)
        x0[31 + n] = BESSEL_C * sinf((float)n * arg) * rinv * fcut;

    // layer 1: 40 -> 64
    float a1[64];
#pragma unroll
    for (int j = 0; j < 64; j++) a1[j] = 0.0f;
    gemv_local<40, 64>(x0, W0, a1);
    float x1[64];
#pragma unroll
    for (int j = 0; j < 64; j++) x1[j] = silu_f(a1[j] * INV_S40);

    // layer 2: 64 -> 128
    float a2[128];
#pragma unroll
    for (int j = 0; j < 128; j++) a2[j] = 0.0f;
    gemv_local<64, 128>(x1, W1, a2);
    float x2[128];
#pragma unroll
    for (int j = 0; j < 128; j++) x2[j] = silu_f(a2[j] * INV_S64);

    // layer 3: 128 -> 128, * fcut -> lat
    float a3[128];
#pragma unroll
    for (int j = 0; j < 128; j++) a3[j] = 0.0f;
    gemv_local<128, 128>(x2, W2, a3);
#pragma unroll
    for (int j = 0; j < 128; j++) g_lat[j * EDGES + e] = a3[j] * INV_S128 * fcut;

    // w_all = lat @ Wenv0 / sqrt(128)
    float a4[128];
#pragma unroll
    for (int j = 0; j < 128; j++) a4[j] = 0.0f;
    gemv_global<128, 128>(g_lat, e, Wenv0, a4);

#pragma unroll
    for (int j = 0; j < 64; j++) g_wedge[j * EDGES + e] = a4[j] * INV_S128;

    float* envp = g_env + 128 * c;
#pragma unroll 4
    for (int m = 0; m < 32; m++) {
        float w0 = a4[64 + 2 * m] * INV_S128;
        float w1 = a4[65 + 2 * m] * INV_S128;
        atomicAdd(envp + 4 * m + 0, w0);
        atomicAdd(envp + 4 * m + 1, w1 * y1);
        atomicAdd(envp + 4 * m + 2, w1 * y2);
        atomicAdd(envp + 4 * m + 3, w1 * y3);
    }
}

// ---------------- pass B1: tensor products -> scal0, s_mix, v_mix ----------------
#define VMIX_COMP(oc, wu, wv, wc)                                  \
    vm[(oc) * 3 + 0] += p2x * (wu) + p3x * (wv) + p4x * (wc);      \
    vm[(oc) * 3 + 1] += p2y * (wu) + p3y * (wv) + p4y * (wc);      \
    vm[(oc) * 3 + 2] += p2z * (wu) + p3z * (wv) + p4z * (wc);

__global__ __launch_bounds__(256) void kB1(
    const int* __restrict__ eidx,
    const float* __restrict__ Ws0, const float* __restrict__ Wv0)
{
    int e = blockIdx.x * blockDim.x + threadIdx.x;
    if (e >= EDGES) return;
    int c = eidx[EDGES + e];
    float y1 = g_Y[0 * EDGES + e];
    float y2 = g_Y[1 * EDGES + e];
    float y3 = g_Y[2 * EDGES + e];

    float sm[32];
    float vm[96];
#pragma unroll
    for (int o = 0; o < 32; o++) sm[o] = 0.0f;
#pragma unroll
    for (int o = 0; o < 96; o++) vm[o] = 0.0f;

    const float* envp = g_env + 128 * c;
#pragma unroll 2
    for (int m = 0; m < 32; m++) {
        float w0 = g_wedge[(2 * m) * EDGES + e];
        float w1 = g_wedge[(2 * m + 1) * EDGES + e];
        float es  = __ldg(envp + 4 * m + 0) * ISN;
        float ev1 = __ldg(envp + 4 * m + 1) * ISN;
        float ev2 = __ldg(envp + 4 * m + 2) * ISN;
        float ev3 = __ldg(envp + 4 * m + 3) * ISN;
        float f1 = w1 * y1, f2 = w1 * y2, f3 = w1 * y3;
        float p0 = w0 * es;
        float p1 = (f1 * ev1 + f2 * ev2 + f3 * ev3) * INV_SQRT3_C;
        g_scal0[m * EDGES + e] = p0;
        g_scal0[(32 + m) * EDGES + e] = p1;
        float p2x = w0 * ev1, p2y = w0 * ev2, p2z = w0 * ev3;
        float p3x = f1 * es,  p3y = f2 * es,  p3z = f3 * es;
        float p4x = (f2 * ev3 - f3 * ev2) * INV_SQRT2_C;
        float p4y = (f3 * ev1 - f1 * ev3) * INV_SQRT2_C;
        float p4z = (f1 * ev2 - f2 * ev1) * INV_SQRT2_C;

        const float4* wsa = reinterpret_cast<const float4*>(Ws0 + m * 32);
        const float4* wsb = reinterpret_cast<const float4*>(Ws0 + (32 + m) * 32);
        const float4* wva = reinterpret_cast<const float4*>(Wv0 + m * 32);
        const float4* wvb = reinterpret_cast<const float4*>(Wv0 + (32 + m) * 32);
        const float4* wvc = reinterpret_cast<const float4*>(Wv0 + (64 + m) * 32);
#pragma unroll
        for (int o = 0; o < 8; o++) {
            float4 A = __ldg(wsa + o), B = __ldg(wsb + o);
            sm[4 * o + 0] += p0 * A.x + p1 * B.x;
            sm[4 * o + 1] += p0 * A.y + p1 * B.y;
            sm[4 * o + 2] += p0 * A.z + p1 * B.z;
            sm[4 * o + 3] += p0 * A.w + p1 * B.w;
            float4 U = __ldg(wva + o), V = __ldg(wvb + o), C4 = __ldg(wvc + o);
            VMIX_COMP(4 * o + 0, U.x, V.x, C4.x);
            VMIX_COMP(4 * o + 1, U.y, V.y, C4.y);
            VMIX_COMP(4 * o + 2, U.z, V.z, C4.z);
            VMIX_COMP(4 * o + 3, U.w, V.w, C4.w);
        }
    }
#pragma unroll
    for (int o = 0; o < 32; o++) g_smix[o * EDGES + e] = sm[o] * INV_S64;
#pragma unroll
    for (int o = 0; o < 96; o++) g_vmix[o * EDGES + e] = vm[o] * INV_S96;
}

// ---------------- pass B2: lat-update MLP + Wenv1 + env1 atomics ----------------
__global__ __launch_bounds__(256) void kB2(
    const int* __restrict__ eidx,
    const float* __restrict__ Wlat0, const float* __restrict__ Wlat1,
    const float* __restrict__ Wenv1)
{
    int e = blockIdx.x * blockDim.x + threadIdx.x;
    if (e >= EDGES) return;
    int c = eidx[EDGES + e];

    float h[128];
#pragma unroll
    for (int j = 0; j < 128; j++) h[j] = 0.0f;
    gemv_global<128, 128>(g_lat, e, Wlat0, h);
    gemv_global<64, 128>(g_scal0, e, Wlat0 + 128 * 128, h);

    float hs[128];
#pragma unroll
    for (int j = 0; j < 128; j++) hs[j] = silu_f(h[j] * INV_S192);

    float nl[128];
#pragma unroll
    for (int j = 0; j < 128; j++) nl[j] = 0.0f;
    gemv_local<128, 128>(hs, Wlat1, nl);

    float fc = g_fcut[e];
    float cn = C_NEW * fc * INV_S128;
#pragma unroll
    for (int j = 0; j < 128; j++) {
        float lo = g_lat[j * EDGES + e];
        g_lat[j * EDGES + e] = C_OLD * lo + cn * nl[j];
    }

    // w_env1 = lat @ Wenv1 / sqrt(128)
    float a[64];
#pragma unroll
    for (int j = 0; j < 64; j++) a[j] = 0.0f;
    gemv_global<128, 64>(g_lat, e, Wenv1, a);

    float y1 = g_Y[0 * EDGES + e];
    float y2 = g_Y[1 * EDGES + e];
    float y3 = g_Y[2 * EDGES + e];
    float* envp = g_env1 + 128 * c;
#pragma unroll 4
    for (int m = 0; m < 32; m++) {
        float w0 = a[2 * m + 0] * INV_S128;
        float w1 = a[2 * m + 1] * INV_S128;
        atomicAdd(envp + 4 * m + 0, w0);
        atomicAdd(envp + 4 * m + 1, w1 * y1);
        atomicAdd(envp + 4 * m + 2, w1 * y2);
        atomicAdd(envp + 4 * m + 3, w1 * y3);
    }
}

// ---------------- pass C1: q products -> scal1 ----------------
__global__ __launch_bounds__(256) void kC1(const int* __restrict__ eidx)
{
    int e = blockIdx.x * blockDim.x + threadIdx.x;
    if (e >= EDGES) return;
    int c = eidx[EDGES + e];
    const float* envp = g_env1 + 128 * c;
#pragma unroll 4
    for (int m = 0; m < 32; m++) {
        float es  = __ldg(envp + 4 * m + 0) * ISN;
        float ev1 = __ldg(envp + 4 * m + 1) * ISN;
        float ev2 = __ldg(envp + 4 * m + 2) * ISN;
        float ev3 = __ldg(envp + 4 * m + 3) * ISN;
        float smv = g_smix[m * EDGES + e];
        float v0 = g_vmix[(m * 3 + 0) * EDGES + e];
        float v1 = g_vmix[(m * 3 + 1) * EDGES + e];
        float v2 = g_vmix[(m * 3 + 2) * EDGES + e];
        g_scal1[m * EDGES + e] = smv * es;
        g_scal1[(32 + m) * EDGES + e] = (v0 * ev1 + v1 * ev2 + v2 * ev3) * INV_SQRT3_C;
    }
}

// ---------------- pass C2: final MLP + output atomics ----------------
__global__ __launch_bounds__(256) void kC2(
    const int* __restrict__ eidx,
    const float* __restrict__ Wfin0, const float* __restrict__ Wfin1,
    float* __restrict__ out)
{
    int e = blockIdx.x * blockDim.x + threadIdx.x;
    if (e >= EDGES) return;
    int c = eidx[EDGES + e];

    float h[128];
#pragma unroll
    for (int j = 0; j < 128; j++) h[j] = 0.0f;
    gemv_global<128, 128>(g_lat, e, Wfin0, h);
    gemv_global<64, 128>(g_scal1, e, Wfin0 + 128 * 128, h);

    float hs[128];
#pragma unroll
    for (int j = 0; j < 128; j++) hs[j] = silu_f(h[j] * INV_S192);

    float nl[128];
#pragma unroll
    for (int j = 0; j < 128; j++) nl[j] = 0.0f;
    gemv_local<128, 128>(hs, Wfin1, nl);

    float fc = g_fcut[e];
    float cn = C_NEW * fc * INV_S128;
    float* op = out + 128 * c;
#pragma unroll 2
    for (int j = 0; j < 128; j++) {
        float lo = g_lat[j * EDGES + e];
        atomicAdd(op + j, (C_OLD * lo + cn * nl[j]) * ISN);
    }
}

// ---------------- launch ----------------
extern "C" void kernel_launch(void* const* d_in, const int* in_sizes, int n_in,
                              void* d_out, int out_size)
{
    const float* coord = (const float*)d_in[0];
    const float* attrs = (const float*)d_in[1];
    const int*   eidx  = (const int*)d_in[2];
    const float* W2b0  = (const float*)d_in[3];
    const float* W2b1  = (const float*)d_in[4];
    const float* W2b2  = (const float*)d_in[5];
    const float* Wenv0 = (const float*)d_in[6];
    const float* Wlat0 = (const float*)d_in[7];
    const float* Wlat1 = (const float*)d_in[8];
    const float* Ws0   = (const float*)d_in[9];
    const float* Wv0   = (const float*)d_in[10];
    const float* Wenv1 = (const float*)d_in[11];
    const float* Wfin0 = (const float*)d_in[12];
    const float* Wfin1 = (const float*)d_in[13];
    float* out = (float*)d_out;

    (void)in_sizes; (void)n_in; (void)out_size;

    const int TPB = 256;
    const int EB = (EDGES + TPB - 1) / TPB;
    const int ZB = (NODES * 128 + TPB - 1) / TPB;

    kZero<<<ZB, TPB>>>(out);
    kA<<<EB, TPB>>>(coord, attrs, eidx, W2b0, W2b1, W2b2, Wenv0);
    kB1<<<EB, TPB>>>(eidx, Ws0, Wv0);
    kB2<<<EB, TPB>>>(eidx, Wlat0, Wlat1, Wenv1);
    kC1<<<EB, TPB>>>(eidx);
    kC2<<<EB, TPB>>>(eidx, Wfin0, Wfin1, out);
}

// round 3
// speedup vs baseline: 2.2858x; 2.2858x over previous
#include <cuda_runtime.h>
#include <math.h>

#define EDGES 320000
#define NODES 10000

// ---------------- scratch buffers (feature-major: [feature][edge]) ----------------
static __device__ float g_x0[40 * EDGES];
static __device__ float g_bufA[128 * EDGES];
static __device__ float g_bufB[128 * EDGES];
static __device__ float g_lat[128 * EDGES];
static __device__ float g_wall[128 * EDGES];
static __device__ float g_scal0[64 * EDGES];
static __device__ float g_scal1[64 * EDGES];
static __device__ float g_smix[32 * EDGES];
static __device__ float g_vmix[96 * EDGES];
static __device__ float g_fcut[EDGES];
static __device__ float g_Y[3 * EDGES];
static __device__ float g_env[NODES * 128];
static __device__ float g_env1[NODES * 128];

// ---------------- constants ----------------
#define INV_RMAX     0.2f
#define SQRT3_C      1.7320508075688772f
#define INV_SQRT3_C  0.5773502691896258f
#define INV_SQRT2_C  0.7071067811865476f
#define ISN          0.17677669529663687f   // 1/sqrt(32)
#define C_OLD        0.8944271909999159f    // 1/sqrt(1.25)
#define C_NEW        0.4472135954999579f
#define INV_S40      0.15811388300841897f
#define INV_S64      0.125f
#define INV_S128     0.08838834764831845f
#define INV_S192     0.07216878364870323f
#define INV_S96      0.10206207261596577f
#define BESSEL_C     0.6324555320336759f    // sqrt(2/5)
#define PI_F         3.14159265358979323846f

// buffer ids
#define AID_X0    0
#define AID_BUFA  1
#define AID_BUFB  2
#define AID_LAT   3
#define AID_WALL  4
#define AID_SCAL0 5
#define AID_SCAL1 6
#define AID_NONE  7

// epilogue ids
#define EPI_NONE       0
#define EPI_SILU       1
#define EPI_SCALE      2
#define EPI_SCALE_FCUT 3
#define EPI_ACC_SILU   4
#define EPI_RESID      5
#define EPI_RESID_ATOM 6

__device__ __forceinline__ float silu_f(float x) {
    return __fdividef(x, 1.0f + __expf(-x));
}

// packed dual-fp32 FMA: d = a*b + c (elementwise on both halves)
__device__ __forceinline__ float2 ffma2(float2 a, float2 b, float2 c) {
    float2 d;
    asm("fma.rn.f32x2 %0, %1, %2, %3;"
        : "=l"(reinterpret_cast<unsigned long long&>(d))
        : "l"(reinterpret_cast<unsigned long long&>(a)),
          "l"(reinterpret_cast<unsigned long long&>(b)),
          "l"(reinterpret_cast<unsigned long long&>(c)));
    return d;
}

template<int ID>
__device__ __forceinline__ float* bufsel() {
    if (ID == AID_X0)    return g_x0;
    if (ID == AID_BUFA)  return g_bufA;
    if (ID == AID_BUFB)  return g_bufB;
    if (ID == AID_LAT)   return g_lat;
    if (ID == AID_WALL)  return g_wall;
    if (ID == AID_SCAL0) return g_scal0;
    if (ID == AID_SCAL1) return g_scal1;
    return nullptr;
}

// ================= tiled GEMM: C[n][e] = sum_k A[k][e] * B[k][n], fused epilogue =========
// BN in {64,128}. BE chosen so BN/8 * BE/8 == 256 threads.
template<int BN, int BE, int EPI, int AID, int CID>
__global__ __launch_bounds__(256, 2) void kGemm(
    const float* __restrict__ B, int K, int N, float scale,
    const int* __restrict__ center, float* __restrict__ outp)
{
    __shared__ __align__(16) float  As[16][BE];
    __shared__ __align__(16) float2 Bs[16][BN];

    const float* A = bufsel<AID>();
    float* C = bufsel<CID>();

    const int t = threadIdx.x;
    const int NG = BN / 8;            // n-groups
    const int eg = t / NG;
    const int ng = t % NG;
    const int e0blk = blockIdx.x * BE;

    float2 acc[8][4];
#pragma unroll
    for (int i = 0; i < 8; i++)
#pragma unroll
        for (int p = 0; p < 4; p++) acc[i][p] = make_float2(0.f, 0.f);

    const int AVEC = 16 * BE / 4 / 256;
    const int BVEC = 16 * BN / 4 / 256;

    for (int k0 = 0; k0 < K; k0 += 16) {
        __syncthreads();
#pragma unroll
        for (int i = 0; i < AVEC; i++) {
            int idx = t + i * 256;
            int row = idx / (BE / 4);
            int col = idx % (BE / 4);
            float4 v = make_float4(0.f, 0.f, 0.f, 0.f);
            if (k0 + row < K)
                v = *reinterpret_cast<const float4*>(A + (size_t)(k0 + row) * EDGES + e0blk + col * 4);
            *reinterpret_cast<float4*>(&As[row][col * 4]) = v;
        }
#pragma unroll
        for (int i = 0; i < BVEC; i++) {
            int idx = t + i * 256;
            int row = idx / (BN / 4);
            int col = idx % (BN / 4);
            float4 v = make_float4(0.f, 0.f, 0.f, 0.f);
            if (k0 + row < K)
                v = *reinterpret_cast<const float4*>(B + (size_t)(k0 + row) * N + col * 4);
            Bs[row][col * 4 + 0] = make_float2(v.x, v.x);
            Bs[row][col * 4 + 1] = make_float2(v.y, v.y);
            Bs[row][col * 4 + 2] = make_float2(v.z, v.z);
            Bs[row][col * 4 + 3] = make_float2(v.w, v.w);
        }
        __syncthreads();
#pragma unroll
        for (int k = 0; k < 16; k++) {
            float4 a01 = *reinterpret_cast<const float4*>(&As[k][eg * 8]);
            float4 a23 = *reinterpret_cast<const float4*>(&As[k][eg * 8 + 4]);
            float2 af[4] = { make_float2(a01.x, a01.y), make_float2(a01.z, a01.w),
                             make_float2(a23.x, a23.y), make_float2(a23.z, a23.w) };
            float4 b01 = *reinterpret_cast<const float4*>(&Bs[k][ng * 8 + 0]);
            float4 b23 = *reinterpret_cast<const float4*>(&Bs[k][ng * 8 + 2]);
            float4 b45 = *reinterpret_cast<const float4*>(&Bs[k][ng * 8 + 4]);
            float4 b67 = *reinterpret_cast<const float4*>(&Bs[k][ng * 8 + 6]);
            float2 bp[8] = { make_float2(b01.x, b01.y), make_float2(b01.z, b01.w),
                             make_float2(b23.x, b23.y), make_float2(b23.z, b23.w),
                             make_float2(b45.x, b45.y), make_float2(b45.z, b45.w),
                             make_float2(b67.x, b67.y), make_float2(b67.z, b67.w) };
#pragma unroll
            for (int n = 0; n < 8; n++)
#pragma unroll
                for (int p = 0; p < 4; p++)
                    acc[n][p] = ffma2(af[p], bp[n], acc[n][p]);
        }
    }

    // ---------------- epilogue ----------------
    const int ebase = e0blk + eg * 8;
    float fc[8];
    int cen[8];
    if (EPI == EPI_SCALE_FCUT || EPI == EPI_RESID || EPI == EPI_RESID_ATOM) {
#pragma unroll
        for (int i = 0; i < 8; i++) fc[i] = g_fcut[ebase + i];
    }
    if (EPI == EPI_RESID_ATOM) {
#pragma unroll
        for (int i = 0; i < 8; i++) cen[i] = center[ebase + i];
    }

#pragma unroll
    for (int n = 0; n < 8; n++) {
        int nn = ng * 8 + n;
        float v[8];
#pragma unroll
        for (int p = 0; p < 4; p++) { v[2 * p] = acc[n][p].x; v[2 * p + 1] = acc[n][p].y; }

        if (EPI == EPI_RESID_ATOM) {
            const float* lo = g_lat + (size_t)nn * EDGES + ebase;
#pragma unroll
            for (int i = 0; i < 8; i++) {
                float val = (C_OLD * lo[i] + C_NEW * scale * fc[i] * v[i]) * ISN;
                atomicAdd(outp + 128 * cen[i] + nn, val);
            }
        } else {
            float* cp = C + (size_t)nn * EDGES + ebase;
            if (EPI == EPI_SCALE) {
#pragma unroll
                for (int i = 0; i < 8; i++) v[i] *= scale;
            } else if (EPI == EPI_SILU) {
#pragma unroll
                for (int i = 0; i < 8; i++) v[i] = silu_f(v[i] * scale);
            } else if (EPI == EPI_SCALE_FCUT) {
#pragma unroll
                for (int i = 0; i < 8; i++) v[i] = v[i] * scale * fc[i];
            } else if (EPI == EPI_ACC_SILU) {
                float4 p0 = *reinterpret_cast<const float4*>(cp);
                float4 p1 = *reinterpret_cast<const float4*>(cp + 4);
                float pv[8] = { p0.x, p0.y, p0.z, p0.w, p1.x, p1.y, p1.z, p1.w };
#pragma unroll
                for (int i = 0; i < 8; i++) v[i] = silu_f((pv[i] + v[i]) * scale);
            } else if (EPI == EPI_RESID) {
                const float* lo = g_lat + (size_t)nn * EDGES + ebase;
                float lv[8];
#pragma unroll
                for (int i = 0; i < 8; i++) lv[i] = lo[i];
#pragma unroll
                for (int i = 0; i < 8; i++) v[i] = C_OLD * lv[i] + C_NEW * scale * fc[i] * v[i];
            }
            *reinterpret_cast<float4*>(cp)     = make_float4(v[0], v[1], v[2], v[3]);
            *reinterpret_cast<float4*>(cp + 4) = make_float4(v[4], v[5], v[6], v[7]);
        }
    }
}

// ---------------- zero init ----------------
__global__ void kZero(float* __restrict__ out) {
    int i = blockIdx.x * blockDim.x + threadIdx.x;
    if (i < NODES * 128) {
        g_env[i] = 0.0f;
        g_env1[i] = 0.0f;
        out[i] = 0.0f;
    }
}

// ---------------- geometry + input features ----------------
__global__ __launch_bounds__(256) void kGeom(
    const float* __restrict__ coord, const float* __restrict__ attrs,
    const int* __restrict__ eidx)
{
    int e = blockIdx.x * blockDim.x + threadIdx.x;
    if (e >= EDGES) return;
    int s = eidx[e];
    int c = eidx[EDGES + e];

    float vx = coord[3 * c + 0] - coord[3 * s + 0];
    float vy = coord[3 * c + 1] - coord[3 * s + 1];
    float vz = coord[3 * c + 2] - coord[3 * s + 2];
    float r2 = vx * vx + vy * vy + vz * vz + 1e-12f;
    float r = sqrtf(r2);
    float u = r * INV_RMAX;
    float u2 = u * u;
    float u6 = u2 * u2 * u2;
    float fcut = 1.0f - 28.0f * u6 + 48.0f * u6 * u - 21.0f * u6 * u2;
    if (u >= 1.0f) fcut = 0.0f;
    float rinv = 1.0f / r;

    g_fcut[e] = fcut;
    g_Y[0 * EDGES + e] = SQRT3_C * vx * rinv;
    g_Y[1 * EDGES + e] = SQRT3_C * vy * rinv;
    g_Y[2 * EDGES + e] = SQRT3_C * vz * rinv;

#pragma unroll
    for (int k = 0; k < 16; k++) g_x0[k * EDGES + e] = attrs[16 * c + k];
#pragma unroll
    for (int k = 0; k < 16; k++) g_x0[(16 + k) * EDGES + e] = attrs[16 * s + k];
    float arg = PI_F * u;
    float bc = BESSEL_C * rinv * fcut;
#pragma unroll
    for (int n = 1; n <= 8; n++)
        g_x0[(31 + n) * EDGES + e] = bc * sinf((float)n * arg);
}

// ---------------- env scatter (atomics) ----------------
__global__ __launch_bounds__(256) void kEnvScatter(const int* __restrict__ eidx, int which)
{
    int e = blockIdx.x * blockDim.x + threadIdx.x;
    if (e >= EDGES) return;
    int c = eidx[EDGES + e];
    const float* w = which ? g_wall : (g_wall + 64 * EDGES);
    float* env = which ? g_env1 : g_env;
    float y1 = g_Y[0 * EDGES + e];
    float y2 = g_Y[1 * EDGES + e];
    float y3 = g_Y[2 * EDGES + e];
    float* envp = env + 128 * c;
#pragma unroll 4
    for (int m = 0; m < 32; m++) {
        float w0 = w[(2 * m + 0) * EDGES + e];
        float w1 = w[(2 * m + 1) * EDGES + e];
        atomicAdd(envp + 4 * m + 0, w0);
        atomicAdd(envp + 4 * m + 1, w1 * y1);
        atomicAdd(envp + 4 * m + 2, w1 * y2);
        atomicAdd(envp + 4 * m + 3, w1 * y3);
    }
}

// ---------------- pass B1: tensor products -> scal0, s_mix, v_mix ----------------
#define VMIX_COMP(oc, wu, wv, wc)                                  \
    vm[(oc) * 3 + 0] += p2x * (wu) + p3x * (wv) + p4x * (wc);      \
    vm[(oc) * 3 + 1] += p2y * (wu) + p3y * (wv) + p4y * (wc);      \
    vm[(oc) * 3 + 2] += p2z * (wu) + p3z * (wv) + p4z * (wc);

__global__ __launch_bounds__(256) void kB1(
    const int* __restrict__ eidx,
    const float* __restrict__ Ws0, const float* __restrict__ Wv0)
{
    int e = blockIdx.x * blockDim.x + threadIdx.x;
    if (e >= EDGES) return;
    int c = eidx[EDGES + e];
    float y1 = g_Y[0 * EDGES + e];
    float y2 = g_Y[1 * EDGES + e];
    float y3 = g_Y[2 * EDGES + e];

    float sm[32];
    float vm[96];
#pragma unroll
    for (int o = 0; o < 32; o++) sm[o] = 0.0f;
#pragma unroll
    for (int o = 0; o < 96; o++) vm[o] = 0.0f;

    const float* envp = g_env + 128 * c;
#pragma unroll 2
    for (int m = 0; m < 32; m++) {
        float w0 = g_wall[(2 * m + 0) * EDGES + e];
        float w1 = g_wall[(2 * m + 1) * EDGES + e];
        float es  = __ldg(envp + 4 * m + 0) * ISN;
        float ev1 = __ldg(envp + 4 * m + 1) * ISN;
        float ev2 = __ldg(envp + 4 * m + 2) * ISN;
        float ev3 = __ldg(envp + 4 * m + 3) * ISN;
        float f1 = w1 * y1, f2 = w1 * y2, f3 = w1 * y3;
        float p0 = w0 * es;
        float p1 = (f1 * ev1 + f2 * ev2 + f3 * ev3) * INV_SQRT3_C;
        g_scal0[m * EDGES + e] = p0;
        g_scal0[(32 + m) * EDGES + e] = p1;
        float p2x = w0 * ev1, p2y = w0 * ev2, p2z = w0 * ev3;
        float p3x = f1 * es,  p3y = f2 * es,  p3z = f3 * es;
        float p4x = (f2 * ev3 - f3 * ev2) * INV_SQRT2_C;
        float p4y = (f3 * ev1 - f1 * ev3) * INV_SQRT2_C;
        float p4z = (f1 * ev2 - f2 * ev1) * INV_SQRT2_C;

        const float4* wsa = reinterpret_cast<const float4*>(Ws0 + m * 32);
        const float4* wsb = reinterpret_cast<const float4*>(Ws0 + (32 + m) * 32);
        const float4* wva = reinterpret_cast<const float4*>(Wv0 + m * 32);
        const float4* wvb = reinterpret_cast<const float4*>(Wv0 + (32 + m) * 32);
        const float4* wvc = reinterpret_cast<const float4*>(Wv0 + (64 + m) * 32);
#pragma unroll
        for (int o = 0; o < 8; o++) {
            float4 A = __ldg(wsa + o), B = __ldg(wsb + o);
            sm[4 * o + 0] += p0 * A.x + p1 * B.x;
            sm[4 * o + 1] += p0 * A.y + p1 * B.y;
            sm[4 * o + 2] += p0 * A.z + p1 * B.z;
            sm[4 * o + 3] += p0 * A.w + p1 * B.w;
            float4 U = __ldg(wva + o), V = __ldg(wvb + o), C4 = __ldg(wvc + o);
            VMIX_COMP(4 * o + 0, U.x, V.x, C4.x);
            VMIX_COMP(4 * o + 1, U.y, V.y, C4.y);
            VMIX_COMP(4 * o + 2, U.z, V.z, C4.z);
            VMIX_COMP(4 * o + 3, U.w, V.w, C4.w);
        }
    }
#pragma unroll
    for (int o = 0; o < 32; o++) g_smix[o * EDGES + e] = sm[o] * INV_S64;
#pragma unroll
    for (int o = 0; o < 96; o++) g_vmix[o * EDGES + e] = vm[o] * INV_S96;
}

// ---------------- pass C1: q products -> scal1 ----------------
__global__ __launch_bounds__(256) void kC1(const int* __restrict__ eidx)
{
    int e = blockIdx.x * blockDim.x + threadIdx.x;
    if (e >= EDGES) return;
    int c = eidx[EDGES + e];
    const float* envp = g_env1 + 128 * c;
#pragma unroll 4
    for (int m = 0; m < 32; m++) {
        float es  = __ldg(envp + 4 * m + 0) * ISN;
        float ev1 = __ldg(envp + 4 * m + 1) * ISN;
        float ev2 = __ldg(envp + 4 * m + 2) * ISN;
        float ev3 = __ldg(envp + 4 * m + 3) * ISN;
        float smv = g_smix[m * EDGES + e];
        float v0 = g_vmix[(m * 3 + 0) * EDGES + e];
        float v1 = g_vmix[(m * 3 + 1) * EDGES + e];
        float v2 = g_vmix[(m * 3 + 2) * EDGES + e];
        g_scal1[m * EDGES + e] = smv * es;
        g_scal1[(32 + m) * EDGES + e] = (v0 * ev1 + v1 * ev2 + v2 * ev3) * INV_SQRT3_C;
    }
}

// ---------------- launch ----------------
extern "C" void kernel_launch(void* const* d_in, const int* in_sizes, int n_in,
                              void* d_out, int out_size)
{
    const float* coord = (const float*)d_in[0];
    const float* attrs = (const float*)d_in[1];
    const int*   eidx  = (const int*)d_in[2];
    const float* W2b0  = (const float*)d_in[3];
    const float* W2b1  = (const float*)d_in[4];
    const float* W2b2  = (const float*)d_in[5];
    const float* Wenv0 = (const float*)d_in[6];
    const float* Wlat0 = (const float*)d_in[7];
    const float* Wlat1 = (const float*)d_in[8];
    const float* Ws0   = (const float*)d_in[9];
    const float* Wv0   = (const float*)d_in[10];
    const float* Wenv1 = (const float*)d_in[11];
    const float* Wfin0 = (const float*)d_in[12];
    const float* Wfin1 = (const float*)d_in[13];
    float* out = (float*)d_out;

    (void)in_sizes; (void)n_in; (void)out_size;

    const int TPB = 256;
    const int EB  = (EDGES + TPB - 1) / TPB;
    const int ZB  = (NODES * 128 + TPB - 1) / TPB;
    const int G128 = EDGES / 128;   // 2500
    const int G256 = EDGES / 256;   // 1250
    const int* center = eidx + EDGES;

    kZero<<<ZB, TPB>>>(out);
    kGeom<<<EB, TPB>>>(coord, attrs, eidx);

    // two-body MLP
    kGemm<64, 256, EPI_SILU,       AID_X0,   AID_BUFA><<<G256, 256>>>(W2b0, 40, 64,  INV_S40,  nullptr, nullptr);
    kGemm<128, 128, EPI_SILU,      AID_BUFA, AID_BUFB><<<G128, 256>>>(W2b1, 64, 128, INV_S64,  nullptr, nullptr);
    kGemm<128, 128, EPI_SCALE_FCUT,AID_BUFB, AID_LAT ><<<G128, 256>>>(W2b2, 128, 128, INV_S128, nullptr, nullptr);
    // env0 projection
    kGemm<128, 128, EPI_SCALE,     AID_LAT,  AID_WALL><<<G128, 256>>>(Wenv0, 128, 128, INV_S128, nullptr, nullptr);
    kEnvScatter<<<EB, TPB>>>(eidx, 0);
    kB1<<<EB, TPB>>>(eidx, Ws0, Wv0);
    // lat update MLP (K = 128 + 64)
    kGemm<128, 128, EPI_NONE,      AID_LAT,  AID_BUFB><<<G128, 256>>>(Wlat0, 128, 128, 1.0f, nullptr, nullptr);
    kGemm<128, 128, EPI_ACC_SILU,  AID_SCAL0,AID_BUFB><<<G128, 256>>>(Wlat0 + 128 * 128, 64, 128, INV_S192, nullptr, nullptr);
    kGemm<128, 128, EPI_RESID,     AID_BUFB, AID_LAT ><<<G128, 256>>>(Wlat1, 128, 128, INV_S128, nullptr, nullptr);
    // env1 projection
    kGemm<64, 256, EPI_SCALE,      AID_LAT,  AID_WALL><<<G256, 256>>>(Wenv1, 128, 64, INV_S128, nullptr, nullptr);
    kEnvScatter<<<EB, TPB>>>(eidx, 1);
    kC1<<<EB, TPB>>>(eidx);
    // final MLP (K = 128 + 64) with fused atomic output scatter
    kGemm<128, 128, EPI_NONE,      AID_LAT,  AID_BUFB><<<G128, 256>>>(Wfin0, 128, 128, 1.0f, nullptr, nullptr);
    kGemm<128, 128, EPI_ACC_SILU,  AID_SCAL1,AID_BUFB><<<G128, 256>>>(Wfin0 + 128 * 128, 64, 128, INV_S192, nullptr, nullptr);
    kGemm<128, 128, EPI_RESID_ATOM,AID_BUFB, AID_NONE><<<G128, 256>>>(Wfin1, 128, 128, INV_S128, center, out);
}

// round 4
// speedup vs baseline: 4.6458x; 2.0325x over previous
#include <cuda_runtime.h>
#include <math.h>

#define EDGES 320000
#define NODES 10000

// ---------------- scratch buffers (feature-major: [feature][edge]) ----------------
static __device__ float g_x0[40 * EDGES];
static __device__ float g_bufA[128 * EDGES];
static __device__ float g_bufB[128 * EDGES];
static __device__ float g_lat[128 * EDGES];
static __device__ float g_wall[128 * EDGES];
static __device__ float g_scal0[64 * EDGES];
static __device__ float g_scal1[64 * EDGES];
static __device__ float g_smix[32 * EDGES];
static __device__ float g_vmix[96 * EDGES];
static __device__ float g_fcut[EDGES];
static __device__ float g_Y[3 * EDGES];
static __device__ float g_env[NODES * 128];
static __device__ float g_env1[NODES * 128];

// ---------------- constants ----------------
#define INV_RMAX     0.2f
#define SQRT3_C      1.7320508075688772f
#define INV_SQRT3_C  0.5773502691896258f
#define INV_SQRT2_C  0.7071067811865476f
#define ISN          0.17677669529663687f   // 1/sqrt(32)
#define C_OLD        0.8944271909999159f    // 1/sqrt(1.25)
#define C_NEW        0.4472135954999579f
#define INV_S40      0.15811388300841897f
#define INV_S64      0.125f
#define INV_S128     0.08838834764831845f
#define INV_S192     0.07216878364870323f
#define INV_S96      0.10206207261596577f
#define BESSEL_C     0.6324555320336759f    // sqrt(2/5)
#define PI_F         3.14159265358979323846f

// buffer ids
#define AID_X0    0
#define AID_BUFA  1
#define AID_BUFB  2
#define AID_LAT   3
#define AID_WALL  4
#define AID_SCAL0 5
#define AID_SCAL1 6
#define AID_NONE  7

// epilogue ids
#define EPI_NONE       0
#define EPI_SILU       1
#define EPI_SCALE      2
#define EPI_SCALE_FCUT 3
#define EPI_RESID      5
#define EPI_RESID_ATOM 6

__device__ __forceinline__ float silu_f(float x) {
    return __fdividef(x, 1.0f + __expf(-x));
}

// packed dual-fp32 FMA: d = a*b + c (elementwise on both halves)
__device__ __forceinline__ float2 ffma2(float2 a, float2 b, float2 c) {
    float2 d;
    asm("fma.rn.f32x2 %0, %1, %2, %3;"
        : "=l"(reinterpret_cast<unsigned long long&>(d))
        : "l"(reinterpret_cast<unsigned long long&>(a)),
          "l"(reinterpret_cast<unsigned long long&>(b)),
          "l"(reinterpret_cast<unsigned long long&>(c)));
    return d;
}

template<int ID>
__device__ __forceinline__ float* bufsel() {
    if (ID == AID_X0)    return g_x0;
    if (ID == AID_BUFA)  return g_bufA;
    if (ID == AID_BUFB)  return g_bufB;
    if (ID == AID_LAT)   return g_lat;
    if (ID == AID_WALL)  return g_wall;
    if (ID == AID_SCAL0) return g_scal0;
    if (ID == AID_SCAL1) return g_scal1;
    return nullptr;
}

// ================= tiled GEMM: C[n][e] = sum_k A[k][e] * B[k][n], fused epilogue =========
// A is [K1 rows of AID] followed by [K2 rows of AID2]. B is (K1+K2) x N row-major.
// Thread tile: 8 edges (4 x float2) x 8 outputs at n = ng + NG*j  (bank-conflict-free LDS.64).
template<int BN, int BE, int EPI, int AID, int AID2, int CID>
__global__ __launch_bounds__(256, 2) void kGemm(
    const float* __restrict__ B, int K1, int K2, int N, float scale,
    const int* __restrict__ center, float* __restrict__ outp)
{
    constexpr int NG  = BN / 8;
    constexpr int AV  = BE / 64;        // float4 A loads / thread / tile
    constexpr int BV  = BN / 64;        // float4 B loads / thread / tile
    constexpr int ARS = 1024 / BE;      // k-rows per A load step
    constexpr int BRS = 1024 / BN;      // k-rows per B load step

    __shared__ __align__(16) float  As[2][16][BE];
    __shared__ __align__(16) float2 Bs[2][16][BN];

    const float* A1 = bufsel<AID>();
    const float* A2 = bufsel<AID2>();
    float* C = bufsel<CID>();

    const int t  = threadIdx.x;
    const int eg = t / NG;
    const int ng = t % NG;
    const int e0 = blockIdx.x * BE;
    const int Kt = K1 + K2;
    const int T  = (Kt + 15) / 16;

    const int ra = t / (BE / 4), ca = t % (BE / 4);
    const int rb = t / (BN / 4), cb = t % (BN / 4);

    float2 acc[8][4];
#pragma unroll
    for (int j = 0; j < 8; j++)
#pragma unroll
        for (int p = 0; p < 4; p++) acc[j][p] = make_float2(0.f, 0.f);

    float4 aS[AV];
    float4 bS[BV];

    // ---- load tile tt into registers ----
#define LOAD_TILE(tt)                                                          \
    {                                                                          \
        int k0 = (tt) * 16;                                                    \
        _Pragma("unroll")                                                      \
        for (int i = 0; i < AV; i++) {                                         \
            int kr = k0 + ra + i * ARS;                                        \
            float4 v = make_float4(0.f, 0.f, 0.f, 0.f);                        \
            if (kr < Kt) {                                                     \
                const float* src = (kr < K1)                                   \
                    ? A1 + (size_t)kr * EDGES                                  \
                    : A2 + (size_t)(kr - K1) * EDGES;                          \
                v = *reinterpret_cast<const float4*>(src + e0 + ca * 4);       \
            }                                                                  \
            aS[i] = v;                                                         \
        }                                                                      \
        _Pragma("unroll")                                                      \
        for (int i = 0; i < BV; i++) {                                         \
            int kr = k0 + rb + i * BRS;                                        \
            float4 v = make_float4(0.f, 0.f, 0.f, 0.f);                        \
            if (kr < Kt)                                                       \
                v = *reinterpret_cast<const float4*>(B + (size_t)kr * N + cb * 4); \
            bS[i] = v;                                                         \
        }                                                                      \
    }

    // ---- store registers into smem buffer ----
#define STORE_TILE(buf)                                                        \
    {                                                                          \
        _Pragma("unroll")                                                      \
        for (int i = 0; i < AV; i++)                                           \
            *reinterpret_cast<float4*>(&As[buf][ra + i * ARS][ca * 4]) = aS[i];\
        _Pragma("unroll")                                                      \
        for (int i = 0; i < BV; i++) {                                         \
            int r = rb + i * BRS, c = cb * 4;                                  \
            Bs[buf][r][c + 0] = make_float2(bS[i].x, bS[i].x);                 \
            Bs[buf][r][c + 1] = make_float2(bS[i].y, bS[i].y);                 \
            Bs[buf][r][c + 2] = make_float2(bS[i].z, bS[i].z);                 \
            Bs[buf][r][c + 3] = make_float2(bS[i].w, bS[i].w);                 \
        }                                                                      \
    }

    LOAD_TILE(0);
    STORE_TILE(0);
    __syncthreads();

    for (int tt = 0; tt < T; tt++) {
        const int buf = tt & 1;
        if (tt + 1 < T) LOAD_TILE(tt + 1);
#pragma unroll
        for (int k = 0; k < 16; k++) {
            float4 a01 = *reinterpret_cast<const float4*>(&As[buf][k][eg * 8]);
            float4 a23 = *reinterpret_cast<const float4*>(&As[buf][k][eg * 8 + 4]);
            float2 af[4] = { make_float2(a01.x, a01.y), make_float2(a01.z, a01.w),
                             make_float2(a23.x, a23.y), make_float2(a23.z, a23.w) };
            float2 bf[8];
#pragma unroll
            for (int j = 0; j < 8; j++) bf[j] = Bs[buf][k][ng + NG * j];
#pragma unroll
            for (int j = 0; j < 8; j++)
#pragma unroll
                for (int p = 0; p < 4; p++)
                    acc[j][p] = ffma2(af[p], bf[j], acc[j][p]);
        }
        if (tt + 1 < T) {
            STORE_TILE(buf ^ 1);
            __syncthreads();
        }
    }
#undef LOAD_TILE
#undef STORE_TILE

    // ---------------- epilogue ----------------
    const int ebase = e0 + eg * 8;
    float fc[8];
    int cen[8];
    if (EPI == EPI_SCALE_FCUT || EPI == EPI_RESID || EPI == EPI_RESID_ATOM) {
#pragma unroll
        for (int i = 0; i < 8; i++) fc[i] = g_fcut[ebase + i];
    }
    if (EPI == EPI_RESID_ATOM) {
#pragma unroll
        for (int i = 0; i < 8; i++) cen[i] = center[ebase + i];
    }

#pragma unroll
    for (int j = 0; j < 8; j++) {
        int nn = ng + NG * j;
        float v[8];
#pragma unroll
        for (int p = 0; p < 4; p++) { v[2 * p] = acc[j][p].x; v[2 * p + 1] = acc[j][p].y; }

        if (EPI == EPI_RESID_ATOM) {
            const float* lo = g_lat + (size_t)nn * EDGES + ebase;
#pragma unroll
            for (int i = 0; i < 8; i++) {
                float val = (C_OLD * lo[i] + C_NEW * scale * fc[i] * v[i]) * ISN;
                atomicAdd(outp + 128 * cen[i] + nn, val);
            }
        } else {
            float* cp = C + (size_t)nn * EDGES + ebase;
            if (EPI == EPI_SCALE) {
#pragma unroll
                for (int i = 0; i < 8; i++) v[i] *= scale;
            } else if (EPI == EPI_SILU) {
#pragma unroll
                for (int i = 0; i < 8; i++) v[i] = silu_f(v[i] * scale);
            } else if (EPI == EPI_SCALE_FCUT) {
#pragma unroll
                for (int i = 0; i < 8; i++) v[i] = v[i] * scale * fc[i];
            } else if (EPI == EPI_RESID) {
                const float* lo = g_lat + (size_t)nn * EDGES + ebase;
#pragma unroll
                for (int i = 0; i < 8; i++) v[i] = C_OLD * lo[i] + C_NEW * scale * fc[i] * v[i];
            }
            *reinterpret_cast<float4*>(cp)     = make_float4(v[0], v[1], v[2], v[3]);
            *reinterpret_cast<float4*>(cp + 4) = make_float4(v[4], v[5], v[6], v[7]);
        }
    }
}

// ---------------- zero init ----------------
__global__ void kZero(float* __restrict__ out) {
    int i = blockIdx.x * blockDim.x + threadIdx.x;
    if (i < NODES * 128) {
        g_env[i] = 0.0f;
        g_env1[i] = 0.0f;
        out[i] = 0.0f;
    }
}

// ---------------- geometry + input features ----------------
__global__ __launch_bounds__(256) void kGeom(
    const float* __restrict__ coord, const float* __restrict__ attrs,
    const int* __restrict__ eidx)
{
    int e = blockIdx.x * blockDim.x + threadIdx.x;
    if (e >= EDGES) return;
    int s = eidx[e];
    int c = eidx[EDGES + e];

    float vx = coord[3 * c + 0] - coord[3 * s + 0];
    float vy = coord[3 * c + 1] - coord[3 * s + 1];
    float vz = coord[3 * c + 2] - coord[3 * s + 2];
    float r2 = vx * vx + vy * vy + vz * vz + 1e-12f;
    float r = sqrtf(r2);
    float u = r * INV_RMAX;
    float u2 = u * u;
    float u6 = u2 * u2 * u2;
    float fcut = 1.0f - 28.0f * u6 + 48.0f * u6 * u - 21.0f * u6 * u2;
    if (u >= 1.0f) fcut = 0.0f;
    float rinv = 1.0f / r;

    g_fcut[e] = fcut;
    g_Y[0 * EDGES + e] = SQRT3_C * vx * rinv;
    g_Y[1 * EDGES + e] = SQRT3_C * vy * rinv;
    g_Y[2 * EDGES + e] = SQRT3_C * vz * rinv;

#pragma unroll
    for (int k = 0; k < 16; k++) g_x0[k * EDGES + e] = attrs[16 * c + k];
#pragma unroll
    for (int k = 0; k < 16; k++) g_x0[(16 + k) * EDGES + e] = attrs[16 * s + k];
    float arg = PI_F * u;
    float bc = BESSEL_C * rinv * fcut;
#pragma unroll
    for (int n = 1; n <= 8; n++)
        g_x0[(31 + n) * EDGES + e] = bc * sinf((float)n * arg);
}

// ---------------- env scatter (atomics) ----------------
__global__ __launch_bounds__(256) void kEnvScatter(const int* __restrict__ eidx, int which)
{
    int e = blockIdx.x * blockDim.x + threadIdx.x;
    if (e >= EDGES) return;
    int c = eidx[EDGES + e];
    const float* w = which ? g_wall : (g_wall + 64 * EDGES);
    float* env = which ? g_env1 : g_env;
    float y1 = g_Y[0 * EDGES + e];
    float y2 = g_Y[1 * EDGES + e];
    float y3 = g_Y[2 * EDGES + e];
    float* envp = env + 128 * c;
#pragma unroll 4
    for (int m = 0; m < 32; m++) {
        float w0 = w[(2 * m + 0) * EDGES + e];
        float w1 = w[(2 * m + 1) * EDGES + e];
        atomicAdd(envp + 4 * m + 0, w0);
        atomicAdd(envp + 4 * m + 1, w1 * y1);
        atomicAdd(envp + 4 * m + 2, w1 * y2);
        atomicAdd(envp + 4 * m + 3, w1 * y3);
    }
}

// ---------------- pass B1: tensor products -> scal0, s_mix, v_mix ----------------
#define VMIX_COMP(oc, wu, wv, wc)                                  \
    vm[(oc) * 3 + 0] += p2x * (wu) + p3x * (wv) + p4x * (wc);      \
    vm[(oc) * 3 + 1] += p2y * (wu) + p3y * (wv) + p4y * (wc);      \
    vm[(oc) * 3 + 2] += p2z * (wu) + p3z * (wv) + p4z * (wc);

__global__ __launch_bounds__(256) void kB1(
    const int* __restrict__ eidx,
    const float* __restrict__ Ws0, const float* __restrict__ Wv0)
{
    int e = blockIdx.x * blockDim.x + threadIdx.x;
    if (e >= EDGES) return;
    int c = eidx[EDGES + e];
    float y1 = g_Y[0 * EDGES + e];
    float y2 = g_Y[1 * EDGES + e];
    float y3 = g_Y[2 * EDGES + e];

    float sm[32];
    float vm[96];
#pragma unroll
    for (int o = 0; o < 32; o++) sm[o] = 0.0f;
#pragma unroll
    for (int o = 0; o < 96; o++) vm[o] = 0.0f;

    const float* envp = g_env + 128 * c;
#pragma unroll 2
    for (int m = 0; m < 32; m++) {
        float w0 = g_wall[(2 * m + 0) * EDGES + e];
        float w1 = g_wall[(2 * m + 1) * EDGES + e];
        float es  = __ldg(envp + 4 * m + 0) * ISN;
        float ev1 = __ldg(envp + 4 * m + 1) * ISN;
        float ev2 = __ldg(envp + 4 * m + 2) * ISN;
        float ev3 = __ldg(envp + 4 * m + 3) * ISN;
        float f1 = w1 * y1, f2 = w1 * y2, f3 = w1 * y3;
        float p0 = w0 * es;
        float p1 = (f1 * ev1 + f2 * ev2 + f3 * ev3) * INV_SQRT3_C;
        g_scal0[m * EDGES + e] = p0;
        g_scal0[(32 + m) * EDGES + e] = p1;
        float p2x = w0 * ev1, p2y = w0 * ev2, p2z = w0 * ev3;
        float p3x = f1 * es,  p3y = f2 * es,  p3z = f3 * es;
        float p4x = (f2 * ev3 - f3 * ev2) * INV_SQRT2_C;
        float p4y = (f3 * ev1 - f1 * ev3) * INV_SQRT2_C;
        float p4z = (f1 * ev2 - f2 * ev1) * INV_SQRT2_C;

        const float4* wsa = reinterpret_cast<const float4*>(Ws0 + m * 32);
        const float4* wsb = reinterpret_cast<const float4*>(Ws0 + (32 + m) * 32);
        const float4* wva = reinterpret_cast<const float4*>(Wv0 + m * 32);
        const float4* wvb = reinterpret_cast<const float4*>(Wv0 + (32 + m) * 32);
        const float4* wvc = reinterpret_cast<const float4*>(Wv0 + (64 + m) * 32);
#pragma unroll
        for (int o = 0; o < 8; o++) {
            float4 A = __ldg(wsa + o), B = __ldg(wsb + o);
            sm[4 * o + 0] += p0 * A.x + p1 * B.x;
            sm[4 * o + 1] += p0 * A.y + p1 * B.y;
            sm[4 * o + 2] += p0 * A.z + p1 * B.z;
            sm[4 * o + 3] += p0 * A.w + p1 * B.w;
            float4 U = __ldg(wva + o), V = __ldg(wvb + o), C4 = __ldg(wvc + o);
            VMIX_COMP(4 * o + 0, U.x, V.x, C4.x);
            VMIX_COMP(4 * o + 1, U.y, V.y, C4.y);
            VMIX_COMP(4 * o + 2, U.z, V.z, C4.z);
            VMIX_COMP(4 * o + 3, U.w, V.w, C4.w);
        }
    }
#pragma unroll
    for (int o = 0; o < 32; o++) g_smix[o * EDGES + e] = sm[o] * INV_S64;
#pragma unroll
    for (int o = 0; o < 96; o++) g_vmix[o * EDGES + e] = vm[o] * INV_S96;
}

// ---------------- pass C1: q products -> scal1 ----------------
__global__ __launch_bounds__(256) void kC1(const int* __restrict__ eidx)
{
    int e = blockIdx.x * blockDim.x + threadIdx.x;
    if (e >= EDGES) return;
    int c = eidx[EDGES + e];
    const float* envp = g_env1 + 128 * c;
#pragma unroll 4
    for (int m = 0; m < 32; m++) {
        float es  = __ldg(envp + 4 * m + 0) * ISN;
        float ev1 = __ldg(envp + 4 * m + 1) * ISN;
        float ev2 = __ldg(envp + 4 * m + 2) * ISN;
        float ev3 = __ldg(envp + 4 * m + 3) * ISN;
        float smv = g_smix[m * EDGES + e];
        float v0 = g_vmix[(m * 3 + 0) * EDGES + e];
        float v1 = g_vmix[(m * 3 + 1) * EDGES + e];
        float v2 = g_vmix[(m * 3 + 2) * EDGES + e];
        g_scal1[m * EDGES + e] = smv * es;
        g_scal1[(32 + m) * EDGES + e] = (v0 * ev1 + v1 * ev2 + v2 * ev3) * INV_SQRT3_C;
    }
}

// ---------------- launch ----------------
extern "C" void kernel_launch(void* const* d_in, const int* in_sizes, int n_in,
                              void* d_out, int out_size)
{
    const float* coord = (const float*)d_in[0];
    const float* attrs = (const float*)d_in[1];
    const int*   eidx  = (const int*)d_in[2];
    const float* W2b0  = (const float*)d_in[3];
    const float* W2b1  = (const float*)d_in[4];
    const float* W2b2  = (const float*)d_in[5];
    const float* Wenv0 = (const float*)d_in[6];
    const float* Wlat0 = (const float*)d_in[7];
    const float* Wlat1 = (const float*)d_in[8];
    const float* Ws0   = (const float*)d_in[9];
    const float* Wv0   = (const float*)d_in[10];
    const float* Wenv1 = (const float*)d_in[11];
    const float* Wfin0 = (const float*)d_in[12];
    const float* Wfin1 = (const float*)d_in[13];
    float* out = (float*)d_out;

    (void)in_sizes; (void)n_in; (void)out_size;

    const int TPB = 256;
    const int EB  = (EDGES + TPB - 1) / TPB;
    const int ZB  = (NODES * 128 + TPB - 1) / TPB;
    const int G128 = EDGES / 128;   // 2500
    const int G256 = EDGES / 256;   // 1250
    const int* center = eidx + EDGES;

    kZero<<<ZB, TPB>>>(out);
    kGeom<<<EB, TPB>>>(coord, attrs, eidx);

    // two-body MLP
    kGemm<64, 256, EPI_SILU,       AID_X0,   AID_NONE, AID_BUFA><<<G256, 256>>>(W2b0, 40, 0, 64,  INV_S40,  nullptr, nullptr);
    kGemm<128, 128, EPI_SILU,      AID_BUFA, AID_NONE, AID_BUFB><<<G128, 256>>>(W2b1, 64, 0, 128, INV_S64,  nullptr, nullptr);
    kGemm<128, 128, EPI_SCALE_FCUT,AID_BUFB, AID_NONE, AID_LAT ><<<G128, 256>>>(W2b2, 128, 0, 128, INV_S128, nullptr, nullptr);
    // env0 projection
    kGemm<128, 128, EPI_SCALE,     AID_LAT,  AID_NONE, AID_WALL><<<G128, 256>>>(Wenv0, 128, 0, 128, INV_S128, nullptr, nullptr);
    kEnvScatter<<<EB, TPB>>>(eidx, 0);
    kB1<<<EB, TPB>>>(eidx, Ws0, Wv0);
    // lat update MLP: fused K = 128 (lat) + 64 (scal0)
    kGemm<128, 128, EPI_SILU,      AID_LAT,  AID_SCAL0, AID_BUFB><<<G128, 256>>>(Wlat0, 128, 64, 128, INV_S192, nullptr, nullptr);
    kGemm<128, 128, EPI_RESID,     AID_BUFB, AID_NONE, AID_LAT ><<<G128, 256>>>(Wlat1, 128, 0, 128, INV_S128, nullptr, nullptr);
    // env1 projection
    kGemm<64, 256, EPI_SCALE,      AID_LAT,  AID_NONE, AID_WALL><<<G256, 256>>>(Wenv1, 128, 0, 64, INV_S128, nullptr, nullptr);
    kEnvScatter<<<EB, TPB>>>(eidx, 1);
    kC1<<<EB, TPB>>>(eidx);
    // final MLP: fused K = 128 (lat) + 64 (scal1), then residual + atomic scatter
    kGemm<128, 128, EPI_SILU,      AID_LAT,  AID_SCAL1, AID_BUFB><<<G128, 256>>>(Wfin0, 128, 64, 128, INV_S192, nullptr, nullptr);
    kGemm<128, 128, EPI_RESID_ATOM,AID_BUFB, AID_NONE, AID_NONE><<<G128, 256>>>(Wfin1, 128, 0, 128, INV_S128, center, out);
}